// round 6
// baseline (speedup 1.0000x reference)
#include <cuda_runtime.h>
#include <cuda_fp16.h>

#define HID 128
#define NMAX 100000
#define NPAD 100096          // NMAX rounded up to 128 for gemm epilogue stores
#define EMAX 1600000
#define GMAX 64
#define SCAN_B 512

// ---- scratch (static device globals; no allocation) ----
__device__ uint2  g_h2h[(size_t)NPAD * 32];   // fp16 messages [N][128], 4 halfs/uint2
__device__ float4 g_acc[(size_t)NMAX * 32];   // aggregated output per layer (fp32)
__device__ float  g_dis[NMAX];                // deg^{-1/2}
__device__ float  g_cnt[GMAX];                // per-graph node counts
__device__ int    g_deg[NMAX];                // in-degree (no self loop)
__device__ int    g_cur[NMAX];                // fill cursor
__device__ int    g_rowptr[NMAX + 1];         // CSR row pointers (by dst)
__device__ int    g_csr[EMAX];                // src ids grouped by dst
__device__ int    g_blksum[(NMAX + SCAN_B - 1) / SCAN_B];

__device__ __forceinline__ int clampi(int v, int hi) {
    return v < 0 ? 0 : (v > hi ? hi : v);
}

// ---- packed f32x2 helpers (Blackwell FFMA2) ----
__device__ __forceinline__ unsigned long long pk2(float x) {
    unsigned long long r;
    asm("mov.b64 %0, {%1, %1};" : "=l"(r) : "f"(x));
    return r;
}
__device__ __forceinline__ void fma2(unsigned long long& d,
                                     unsigned long long a, unsigned long long b) {
    asm("fma.rn.f32x2 %0, %1, %2, %0;" : "+l"(d) : "l"(a), "l"(b));
}
__device__ __forceinline__ float2 up2(unsigned long long v) {
    float2 f;
    asm("mov.b64 {%0, %1}, %2;" : "=f"(f.x), "=f"(f.y) : "l"(v));
    return f;
}

// ---------------------------------------------------------------------------
__global__ void k_init(float* __restrict__ out, int N, int out_elems) {
    int i = blockIdx.x * blockDim.x + threadIdx.x;
    if (i < N) { g_deg[i] = 0; g_cur[i] = 0; }
    if (i < GMAX) g_cnt[i] = 0.0f;
    if (i < out_elems) out[i] = 0.0f;
}

__global__ void k_count(const int* __restrict__ dst, int E, int N) {
    int e = blockIdx.x * blockDim.x + threadIdx.x;
    if (e < E) atomicAdd(&g_deg[clampi(dst[e], N - 1)], 1);
}

// --- exclusive scan of g_deg -> g_rowptr ---
__global__ void k_scan1(int N) {
    __shared__ int sm[SCAN_B];
    int t = threadIdx.x;
    int i = blockIdx.x * SCAN_B + t;
    int v = (i < N) ? g_deg[i] : 0;
    sm[t] = v;
    __syncthreads();
    #pragma unroll
    for (int off = 1; off < SCAN_B; off <<= 1) {
        int x = (t >= off) ? sm[t - off] : 0;
        __syncthreads();
        sm[t] += x;
        __syncthreads();
    }
    if (i < N) g_rowptr[i] = sm[t] - v;          // exclusive
    if (t == SCAN_B - 1) g_blksum[blockIdx.x] = sm[t];
}

// parallel exclusive scan of block sums (nb <= SCAN_B)
__global__ void k_scan2(int nb) {
    __shared__ int sm[SCAN_B];
    int t = threadIdx.x;
    int v = (t < nb) ? g_blksum[t] : 0;
    sm[t] = v;
    __syncthreads();
    #pragma unroll
    for (int off = 1; off < SCAN_B; off <<= 1) {
        int x = (t >= off) ? sm[t - off] : 0;
        __syncthreads();
        sm[t] += x;
        __syncthreads();
    }
    if (t < nb) g_blksum[t] = sm[t] - v;
}

// add block offsets + compute dis = rsqrt(deg+1)
__global__ void k_scan3(int N, int E) {
    int i = blockIdx.x * blockDim.x + threadIdx.x;
    if (i < N) {
        g_rowptr[i] += g_blksum[i / SCAN_B];
        g_dis[i] = rsqrtf((float)(g_deg[i] + 1));
    }
    if (i == 0) g_rowptr[N] = E;
}

__global__ void k_fill(const int* __restrict__ src,
                       const int* __restrict__ dst, int E, int N) {
    int e = blockIdx.x * blockDim.x + threadIdx.x;
    if (e >= E) return;
    int d = clampi(dst[e], N - 1);
    int pos = atomicAdd(&g_cur[d], 1);
    int idx = clampi(g_rowptr[d] + pos, EMAX - 1);
    g_csr[idx] = clampi(src[e], N - 1);
}

// ---------------------------------------------------------------------------
// GEMM: h2h = fp16( f(in) @ W )
// f(in) = in (layer 0) ; relu(in + bias_prev) (layers > 0, in = g_acc)
// 256 threads, 128x128 tile. FFMA2 (f32x2) inner loop, columns paired.
// smem: xs_t [128 k][128 m] XOR-swizzled (transposed A) + ws [128 k][128 n].
// ws is reused as fp32 staging for the fp16 epilogue.
// ---------------------------------------------------------------------------
__global__ void __launch_bounds__(256) k_gemm(
    const float* __restrict__ xin,
    const float* __restrict__ W,
    const float* __restrict__ bias,
    int use_acc,
    int N)
{
    extern __shared__ float sm[];
    float* xs = sm;                 // [128][128] transposed + swizzled
    float* ws = sm + 128 * HID;     // [128][128] W, k-major rows

    const int tid  = threadIdx.x;
    const int base = blockIdx.x * 128;
    const int tx   = tid & 15;
    const int ty   = tid >> 4;

    // --- load W straight: ws[k][n] ---
    {
        const float4* Wv = (const float4*)W;
        #pragma unroll
        for (int i = 0; i < 16; i++) {
            int o = i * 256 + tid;          // 4096 float4
            int k = o >> 5, q = o & 31;
            *(float4*)(ws + k * HID + q * 4) = Wv[o];
        }
    }
    // --- load x tile transposed + swizzled: xs[k*128 + ((m>>2 ^ (k>>2)&7)<<2) + (m&3)]
    {
        #pragma unroll
        for (int i = 0; i < 16; i++) {
            int o = i * 256 + tid;
            int r = o >> 5;                 // row (m), warp-uniform
            int q = o & 31;                 // float4 index: k = 4q..4q+3
            float4 v = make_float4(0.f, 0.f, 0.f, 0.f);
            if (base + r < N) {
                if (use_acc) {
                    v = g_acc[(size_t)(base + r) * 32 + q];
                    int k4 = q * 4;
                    v.x = fmaxf(v.x + bias[k4 + 0], 0.0f);
                    v.y = fmaxf(v.y + bias[k4 + 1], 0.0f);
                    v.z = fmaxf(v.z + bias[k4 + 2], 0.0f);
                    v.w = fmaxf(v.w + bias[k4 + 3], 0.0f);
                } else {
                    v = ((const float4*)(xin + (size_t)(base + r) * HID))[q];
                }
            }
            int sw = q & 7;                 // (k>>2)&7 for k=4q+j
            int mcol = (((r >> 2) ^ sw) << 2) + (r & 3);
            float vv[4] = {v.x, v.y, v.z, v.w};
            #pragma unroll
            for (int j = 0; j < 4; j++)
                xs[(4 * q + j) * HID + mcol] = vv[j];
        }
    }
    __syncthreads();

    // rows: m = 4*tx+i (i<4) and 64+4*tx+(i-4) (i>=4)
    // cols: n-pairs: (ty*4+0,1),(ty*4+2,3),(64+ty*4+0,1),(64+ty*4+2,3)
    unsigned long long acc[8][4];
    #pragma unroll
    for (int i = 0; i < 8; i++)
        #pragma unroll
        for (int j = 0; j < 4; j++) acc[i][j] = 0ull;

    #pragma unroll 4
    for (int k = 0; k < HID; k++) {
        int sw = (k >> 2) & 7;
        float4 a0 = *(const float4*)(xs + k * HID + ((tx ^ sw) << 2));
        float4 a1 = *(const float4*)(xs + k * HID + (((16 + tx) ^ sw) << 2));
        ulonglong2 b0 = *(const ulonglong2*)(ws + k * HID + ty * 4);
        ulonglong2 b1 = *(const ulonglong2*)(ws + k * HID + 64 + ty * 4);
        float av[8] = {a0.x, a0.y, a0.z, a0.w, a1.x, a1.y, a1.z, a1.w};
        #pragma unroll
        for (int i = 0; i < 8; i++) {
            unsigned long long ap = pk2(av[i]);
            fma2(acc[i][0], ap, b0.x);
            fma2(acc[i][1], ap, b0.y);
            fma2(acc[i][2], ap, b1.x);
            fma2(acc[i][3], ap, b1.y);
        }
    }

    // --- epilogue: stage fp32 into ws, then coalesced fp16 stores ---
    __syncthreads();           // everyone done reading ws
    #pragma unroll
    for (int i = 0; i < 8; i++) {
        int m = (i < 4) ? (4 * tx + i) : (64 + 4 * tx + (i - 4));
        float* row = ws + m * HID + ty * 4;
        float2 c0 = up2(acc[i][0]);
        float2 c1 = up2(acc[i][1]);
        float2 c2 = up2(acc[i][2]);
        float2 c3 = up2(acc[i][3]);
        *(float2*)(row)          = c0;
        *(float2*)(row + 2)      = c1;
        *(float2*)(row + 64)     = c2;
        *(float2*)(row + 64 + 2) = c3;
    }
    __syncthreads();

    // convert 64 contiguous floats per thread -> 8 x uint4 (8 halfs each)
    {
        const float4* srcv = (const float4*)ws + tid * 16;
        uint4* dst = (uint4*)g_h2h;
        size_t h4 = ((size_t)base * HID + (size_t)tid * 64) >> 3;  // uint4 index
        #pragma unroll
        for (int i = 0; i < 8; i++) {
            float4 p = srcv[i * 2];
            float4 q = srcv[i * 2 + 1];
            __half2 h0 = __floats2half2_rn(p.x, p.y);
            __half2 h1 = __floats2half2_rn(p.z, p.w);
            __half2 h2 = __floats2half2_rn(q.x, q.y);
            __half2 h3 = __floats2half2_rn(q.z, q.w);
            uint4 u;
            u.x = *(unsigned*)&h0; u.y = *(unsigned*)&h1;
            u.z = *(unsigned*)&h2; u.w = *(unsigned*)&h3;
            dst[h4 + i] = u;
        }
    }
}

// ---------------------------------------------------------------------------
// gather-aggregate: one warp per dst node, fp16 messages, fp32 accumulate.
// acc[n] = h2[n]*dis[n]^2 + sum_{s in in(n)} h2[s]*dis[s]*dis[n]
// ---------------------------------------------------------------------------
__global__ void __launch_bounds__(256) k_aggr(int N) {
    int w    = (int)((blockIdx.x * (unsigned)blockDim.x + threadIdx.x) >> 5);
    int lane = threadIdx.x & 31;
    if (w >= N) return;

    int beg = clampi(g_rowptr[w],     EMAX);
    int end = clampi(g_rowptr[w + 1], EMAX);
    float dn = g_dis[w];

    uint2 u = g_h2h[(size_t)w * 32 + lane];
    float2 f0 = __half22float2(*(__half2*)&u.x);
    float2 f1 = __half22float2(*(__half2*)&u.y);
    float sn = dn * dn;
    float4 a = make_float4(f0.x * sn, f0.y * sn, f1.x * sn, f1.y * sn);

    for (int e = beg; e < end; e++) {
        int s = g_csr[e];
        float nm = dn * g_dis[s];
        uint2 v = g_h2h[(size_t)s * 32 + lane];
        float2 g0 = __half22float2(*(__half2*)&v.x);
        float2 g1 = __half22float2(*(__half2*)&v.y);
        a.x += g0.x * nm; a.y += g0.y * nm;
        a.z += g1.x * nm; a.w += g1.y * nm;
    }
    g_acc[(size_t)w * 32 + lane] = a;
}

// ---------------------------------------------------------------------------
// pooling (batch sorted): running sums, flush on graph-id change
// ---------------------------------------------------------------------------
#define POOL_CHUNK 256
__global__ void __launch_bounds__(HID) k_pool(
    const int* __restrict__ batch,
    const float* __restrict__ bias,
    float* __restrict__ out,
    int N)
{
    int j     = threadIdx.x;
    int start = blockIdx.x * POOL_CHUNK;
    if (start >= N) return;
    int end = start + POOL_CHUNK;
    if (end > N) end = N;

    const float* accf = (const float*)g_acc;

    float b   = bias[j];
    int   cur = clampi(batch[start], GMAX - 1);
    float sum = 0.0f;
    float cnt = 0.0f;

    for (int r = start; r < end; r++) {
        int g = clampi(batch[r], GMAX - 1);
        if (g != cur) {
            atomicAdd(out + (size_t)cur * HID + j, sum);
            if (j == 0) atomicAdd(&g_cnt[cur], cnt);
            sum = 0.0f; cnt = 0.0f; cur = g;
        }
        sum += fmaxf(accf[(size_t)r * HID + j] + b, 0.0f);
        cnt += 1.0f;
    }
    atomicAdd(out + (size_t)cur * HID + j, sum);
    if (j == 0) atomicAdd(&g_cnt[cur], cnt);
}

__global__ void k_div(float* __restrict__ out, int out_elems) {
    int i = blockIdx.x * blockDim.x + threadIdx.x;
    if (i < out_elems) out[i] /= fmaxf(g_cnt[i >> 7], 1.0f);
}

// ---------------------------------------------------------------------------
extern "C" void kernel_launch(void* const* d_in, const int* in_sizes, int n_in,
                              void* d_out, int out_size) {
    const float* x     = (const float*)d_in[0];
    const int*   ei    = (const int*)d_in[1];     // int32 (JAX x64 disabled)
    const int*   batch = (const int*)d_in[2];     // int32
    const float* Ws    = (const float*)d_in[3];
    const float* bs    = (const float*)d_in[4];
    float*       out   = (float*)d_out;

    const int N = in_sizes[0] / HID;
    const int E = in_sizes[1] / 2;
    const int* srcp = ei;
    const int* dstp = ei + E;

    const size_t smem = 2 * 128 * HID * sizeof(float);   // 128 KB
    cudaFuncSetAttribute(k_gemm, cudaFuncAttributeMaxDynamicSharedMemorySize,
                         (int)smem);

    const int nb_scan = (N + SCAN_B - 1) / SCAN_B;

    k_init  <<<(N + 255) / 256, 256>>>(out, N, out_size);
    k_count <<<(E + 255) / 256, 256>>>(dstp, E, N);
    k_scan1 <<<nb_scan, SCAN_B>>>(N);
    k_scan2 <<<1, SCAN_B>>>(nb_scan);
    k_scan3 <<<(N + 255) / 256, 256>>>(N, E);
    k_fill  <<<(E + 255) / 256, 256>>>(srcp, dstp, E, N);

    const int gemm_blocks = (N + 127) / 128;
    const int aggr_blocks = (int)(((long long)N * 32 + 255) / 256);

    for (int l = 0; l < 3; l++) {
        const float* bias_prev = (l == 0) ? bs : (bs + (size_t)(l - 1) * HID);
        k_gemm<<<gemm_blocks, 256, smem>>>(
            x, Ws + (size_t)l * HID * HID, bias_prev, l > 0 ? 1 : 0, N);
        k_aggr<<<aggr_blocks, 256>>>(N);
    }

    k_pool<<<(N + POOL_CHUNK - 1) / POOL_CHUNK, HID>>>(batch, bs + 2 * HID, out, N);
    k_div <<<(out_size + 255) / 256, 256>>>(out, out_size);
}